// round 16
// baseline (speedup 1.0000x reference)
#include <cuda_runtime.h>
#include <cuda_fp16.h>
#include <cstdint>
#include <math.h>

// Problem constants
constexpr int BATCH = 4;
constexpr int SEQ   = 4096;
constexpr int EMB   = 1024;
constexpr int HD    = 64;
constexpr int ROWS  = BATCH * SEQ;

constexpr int P32  = 36;            // u32 pitch for 64-col f16 tile rows
constexpr int PH   = 72;            // same pitch in halves
constexpr int TSZ  = 64 * P32;      // u32 per tile component (2304)
constexpr int TSZB = TSZ * 4;       // bytes (9216)
constexpr int SLOTB = 2 * TSZB;     // K hi + V^T hi per tile slot (18432)

// Q prescale: (1/8) * log2(e)  -> scores are direct exp2 arguments
constexpr float QSCALE = 0.125f * 1.44269504088896340736f;

// Pre-split fp16 scratch (device globals; 16B aligned for cp.async)
__device__ __align__(16) uint32_t g_Qhi[ROWS * 32];             // Q*QSCALE, fp16
__device__ __align__(16) uint32_t g_Ksp[BATCH * 64 * TSZ];      // [tile] K-major hi
__device__ __align__(16) uint32_t g_Vsp[BATCH * 64 * TSZ];      // [tile] V^T hi
__device__ __align__(16) uint32_t g_Wsp[3 * 16 * 2 * TSZ];      // W^T fp16 image per chunk

// ---------------------------------------------------------------------------
// helpers
// ---------------------------------------------------------------------------
__device__ __forceinline__ uint32_t pack_h2(float a, float b) {
    uint32_t h;
    asm("cvt.rn.f16x2.f32 %0, %1, %2;" : "=r"(h) : "f"(b), "f"(a));
    return h;   // low half = a, high half = b
}
__device__ __forceinline__ void split2pack(float a, float b,
                                           uint32_t& hi, uint32_t& lo) {
    hi = pack_h2(a, b);
    __half2 h2 = *(__half2*)&hi;
    lo = pack_h2(a - __low2float(h2), b - __high2float(h2));
}
__device__ __forceinline__ float ex2f(float x) {
    float r;
    asm("ex2.approx.f32 %0, %1;" : "=f"(r) : "f"(x));
    return r;
}

__device__ __forceinline__ void mma16816(float* d, const uint32_t* a,
                                         uint32_t b0, uint32_t b1) {
    asm volatile(
        "mma.sync.aligned.m16n8k16.row.col.f32.f16.f16.f32 "
        "{%0,%1,%2,%3}, {%4,%5,%6,%7}, {%8,%9}, {%0,%1,%2,%3};"
        : "+f"(d[0]), "+f"(d[1]), "+f"(d[2]), "+f"(d[3])
        : "r"(a[0]), "r"(a[1]), "r"(a[2]), "r"(a[3]), "r"(b0), "r"(b1));
}

__device__ __forceinline__ void ldm_x4(uint32_t* r, uint32_t addr) {
    asm volatile("ldmatrix.sync.aligned.m8n8.x4.shared.b16 {%0,%1,%2,%3}, [%4];"
                 : "=r"(r[0]), "=r"(r[1]), "=r"(r[2]), "=r"(r[3]) : "r"(addr));
}

__device__ __forceinline__ void cpasync16(uint32_t saddr, const void* gptr) {
    asm volatile("cp.async.cg.shared.global [%0], [%1], 16;"
                 :: "r"(saddr), "l"(gptr) : "memory");
}
#define CP_COMMIT() asm volatile("cp.async.commit_group;" ::: "memory")
#define CP_WAIT(n)  asm volatile("cp.async.wait_group %0;" :: "n"(n) : "memory")

// ---------------------------------------------------------------------------
// Kernel 0: pre-split W^T fp16 images, smem-staged so global stores coalesce.
// ---------------------------------------------------------------------------
__global__ __launch_bounds__(256) void wsplit_kernel(
    const float* __restrict__ Wq, const float* __restrict__ Wk,
    const float* __restrict__ Wv)
{
    __shared__ float ws[64 * 65];
    const int m  = blockIdx.x;
    const int kb = blockIdx.y;
    const float* W = (m == 0) ? Wq : (m == 1) ? Wk : Wv;
    const int tid = threadIdx.x;

#pragma unroll
    for (int i = 0; i < 4; i++) {
        int idx = tid + i * 256;
        int r   = idx >> 4;
        int c4  = (idx & 15) * 4;
        float4 v = *(const float4*)&W[(size_t)(kb * 64 + r) * HD + c4];
        float* d = &ws[r * 65 + c4];
        d[0] = v.x; d[1] = v.y; d[2] = v.z; d[3] = v.w;
    }
    __syncthreads();

    uint32_t* hiO = g_Wsp + (size_t)(m * 16 + kb) * 2 * TSZ;
    uint32_t* loO = hiO + TSZ;
#pragma unroll
    for (int i = 0; i < 8; i++) {
        int idx = tid + i * 256;
        int c   = idx >> 5;
        int rp  = idx & 31;
        float a = ws[(rp * 2) * 65 + c];
        float b = ws[(rp * 2 + 1) * 65 + c];
        uint32_t h, l;
        split2pack(a, b, h, l);
        hiO[c * P32 + rp] = h;
        loO[c * P32 + rp] = l;
    }
}

// ---------------------------------------------------------------------------
// Kernel 1: QKV projection, 2-term fp16 split (R12 structure, unchanged).
// grid (3, 128), 3 CTAs/SM.  Q output pre-scaled by QSCALE.
// ---------------------------------------------------------------------------
constexpr int QKV_SMEM = (128 * P32 + 2 * TSZ) * 4;   // 36864 B

__global__ __launch_bounds__(256, 3) void qkv_mma7(
    const float* __restrict__ x,
    const float* __restrict__ bq, const float* __restrict__ bk,
    const float* __restrict__ bv)
{
    extern __shared__ __align__(16) uint32_t qsm[];
    uint32_t* sXhi = qsm;
    const uint32_t sb    = (uint32_t)__cvta_generic_to_shared(qsm);
    const uint32_t sXhiB = sb;
    const uint32_t sWhB  = sb + 128 * P32 * 4;
    const uint32_t sWlB  = sWhB + TSZB;

    const int tid = threadIdx.x;
    const int w   = tid >> 5;
    const int ln  = tid & 31;
    const int g   = ln >> 2;
    const int t4  = ln & 3;
    const int m    = blockIdx.x;
    const int row0 = blockIdx.y * 128;

    const int roA = ((ln >> 3) & 1) * 8 + (ln & 7);
    const int kbA = ((ln >> 4) & 1) * 16;
    const int roB = ((ln >> 4) & 1) * 8 + (ln & 7);
    const int kbB = ((ln >> 3) & 1) * 16;
    const uint32_t aHi = sXhiB + (w * 16 + roA) * 144 + kbA;
    const uint32_t bHi = sWhB + roB * 144 + kbB;
    const uint32_t bLo = sWlB + roB * 144 + kbB;

    float acc[32];
#pragma unroll
    for (int i = 0; i < 32; i++) acc[i] = 0.f;

    for (int kb = 0; kb < 16; kb++) {
        {
            const char* src = (const char*)(g_Wsp + (size_t)(m * 16 + kb) * 2 * TSZ);
            for (int i = tid; i < 1152; i += 256)
                cpasync16(sWhB + i * 16, src + i * 16);
            CP_COMMIT();
        }
        // stage x tile 128x64, hi only
#pragma unroll
        for (int i = 0; i < 8; i++) {
            int idx = tid + i * 256;
            int r   = idx >> 4;
            int c4  = (idx & 15) * 4;
            float4 v = *(const float4*)&x[(size_t)(row0 + r) * EMB + kb * 64 + c4];
            int o = r * P32 + (c4 >> 1);
            sXhi[o]     = pack_h2(v.x, v.y);
            sXhi[o + 1] = pack_h2(v.z, v.w);
        }
        CP_WAIT(0);
        __syncthreads();

#pragma unroll
        for (int kk = 0; kk < 4; kk++) {
            uint32_t ah[4];
            ldm_x4(ah, aHi + kk * 32);
#pragma unroll
            for (int j = 0; j < 4; j++) {
                uint32_t bh[4], bl[4];
                ldm_x4(bh, bHi + j * 16 * 144 + kk * 32);
                ldm_x4(bl, bLo + j * 16 * 144 + kk * 32);
                float* d0 = &acc[(2 * j) * 4];
                float* d1 = &acc[(2 * j + 1) * 4];
                mma16816(d0, ah, bh[0], bh[1]);
                mma16816(d0, ah, bl[0], bl[1]);
                mma16816(d1, ah, bh[2], bh[3]);
                mma16816(d1, ah, bl[2], bl[3]);
            }
        }
        __syncthreads();
    }

    // epilogue: bias (+QSCALE for Q) + fp16 round + store images
    const int r0  = row0 + w * 16 + g;
    const int ktf = r0 >> 6;
    const int rr  = r0 & 63;

    if (m == 0) {
#pragma unroll
        for (int nb = 0; nb < 8; nb++) {
            int hc = nb * 8 + t4 * 2;
            float2 bb = *(const float2*)&bq[hc];
            g_Qhi[(size_t)r0 * 32 + (hc >> 1)] =
                pack_h2((acc[nb * 4 + 0] + bb.x) * QSCALE,
                        (acc[nb * 4 + 1] + bb.y) * QSCALE);
            g_Qhi[(size_t)(r0 + 8) * 32 + (hc >> 1)] =
                pack_h2((acc[nb * 4 + 2] + bb.x) * QSCALE,
                        (acc[nb * 4 + 3] + bb.y) * QSCALE);
        }
    } else if (m == 1) {
        uint32_t* kHI = g_Ksp + (size_t)ktf * TSZ;
#pragma unroll
        for (int nb = 0; nb < 8; nb++) {
            int hc = nb * 8 + t4 * 2;
            float2 bb = *(const float2*)&bk[hc];
            kHI[rr * P32 + (hc >> 1)] =
                pack_h2(acc[nb * 4 + 0] + bb.x, acc[nb * 4 + 1] + bb.y);
            kHI[(rr + 8) * P32 + (hc >> 1)] =
                pack_h2(acc[nb * 4 + 2] + bb.x, acc[nb * 4 + 3] + bb.y);
        }
    } else {
        unsigned short* vHI = (unsigned short*)(g_Vsp + (size_t)ktf * TSZ);
#pragma unroll
        for (int nb = 0; nb < 8; nb++) {
            int hc = nb * 8 + t4 * 2;
            float2 bb = *(const float2*)&bv[hc];
            uint32_t h = pack_h2(acc[nb * 4 + 0] + bb.x, acc[nb * 4 + 1] + bb.y);
            vHI[hc * PH + rr]       = (unsigned short)(h & 0xffff);
            vHI[(hc + 1) * PH + rr] = (unsigned short)(h >> 16);
            h = pack_h2(acc[nb * 4 + 2] + bb.x, acc[nb * 4 + 3] + bb.y);
            vHI[hc * PH + rr + 8]       = (unsigned short)(h & 0xffff);
            vHI[(hc + 1) * PH + rr + 8] = (unsigned short)(h >> 16);
        }
    }
}

// ---------------------------------------------------------------------------
// Kernel 2: balanced causal flash attention, double-tile iterations with
// WARP-PARITY TILE ORDER: odd warps process (b, a), even warps (a, b), so
// one parity's exp/MUFU phase overlaps the other's QK tensor phase.
// 512 thr, grid (32, BATCH); 3-pair (6-slot) cp.async ring.
// ---------------------------------------------------------------------------
constexpr int RP = 37;
constexpr int PAIRB = 2 * SLOTB;                            // 36864 B
constexpr int FLASH_SMEM = 3 * PAIRB + 2 * 128 * RP * 4;    // 148480 B

__global__ __launch_bounds__(512) void flash_mmaB(float* __restrict__ out)
{
    extern __shared__ __align__(16) uint32_t fsm[];
    float* redA = (float*)(fsm + 6 * 2 * TSZ);
    float* redB = redA + 128 * RP;

    const uint32_t sb = (uint32_t)__cvta_generic_to_shared(fsm);
    const int tid = threadIdx.x;
    const int w   = tid >> 5;
    const int ln  = tid & 31;
    const int g   = ln >> 2;
    const int t4  = ln & 3;
    const int wr  = w & 3;
    const int wc  = w >> 2;
    const int c   = blockIdx.x;
    const int b   = blockIdx.y;

    const int roB = ((ln >> 4) & 1) * 8 + (ln & 7);
    const int kbB = ((ln >> 3) & 1) * 16;

    const int qts[2] = {c, 63 - c};

    for (int p = 0; p < 2; p++) {
        const int qt    = qts[p];
        const int nkt   = qt + 1;
        const int npair = (nkt + 1) >> 1;

        const size_t rowg = (size_t)b * SEQ + qt * 64 + wr * 16 + g;
        uint32_t qfh[16];
#pragma unroll
        for (int kk = 0; kk < 4; kk++) {
            qfh[kk * 4 + 0] = g_Qhi[rowg * 32 + kk * 8 + t4];
            qfh[kk * 4 + 1] = g_Qhi[(rowg + 8) * 32 + kk * 8 + t4];
            qfh[kk * 4 + 2] = g_Qhi[rowg * 32 + kk * 8 + t4 + 4];
            qfh[kk * 4 + 3] = g_Qhi[(rowg + 8) * 32 + kk * 8 + t4 + 4];
        }

        float o[32];
#pragma unroll
        for (int i = 0; i < 32; i++) o[i] = 0.f;
        float l0 = 0.f, l1 = 0.f;
        const int qrow0 = qt * 64 + wr * 16 + g;
        const int qrow1 = qrow0 + 8;

        auto fill_tile = [&](uint32_t d, int t) {
            const char* sK = (const char*)(g_Ksp + (size_t)(b * 64 + t) * TSZ);
            const char* sV = (const char*)(g_Vsp + (size_t)(b * 64 + t) * TSZ);
            for (int i = tid; i < 576; i += 512)
                cpasync16(d + i * 16, sK + i * 16);
            for (int i = tid; i < 576; i += 512)
                cpasync16(d + TSZB + i * 16, sV + i * 16);
        };
        auto fill_pair = [&](int pr) {
            uint32_t d = sb + (pr % 3) * PAIRB;
            int t0 = 2 * pr;
            fill_tile(d, t0);
            if (t0 + 1 < 64) fill_tile(d + SLOTB, t0 + 1);
        };

        fill_pair(0);
        CP_COMMIT();
        if (npair > 1) fill_pair(1);
        CP_COMMIT();
        CP_WAIT(1);
        __syncthreads();

        auto compute_tile = [&](uint32_t base, int kt) {
            const uint32_t kAddr = base + (wc * 16 + roB) * 144 + kbB;
            const uint32_t vAddr = base + TSZB + roB * 144 + wc * 32 + kbB;

            float s[8];
#pragma unroll
            for (int i = 0; i < 8; i++) s[i] = 0.f;
#pragma unroll
            for (int kk = 0; kk < 4; kk++) {
                uint32_t bh[4];
                ldm_x4(bh, kAddr + kk * 32);
                const uint32_t* ah = &qfh[kk * 4];
                mma16816(&s[0], ah, bh[0], bh[1]);
                mma16816(&s[4], ah, bh[2], bh[3]);
            }

            const bool msk = (kt == qt);
#pragma unroll
            for (int nb = 0; nb < 2; nb++) {
                int k0 = kt * 64 + wc * 16 + nb * 8 + t4 * 2;
                float p0 = ex2f(s[nb * 4 + 0]);
                float p1 = ex2f(s[nb * 4 + 1]);
                float p2 = ex2f(s[nb * 4 + 2]);
                float p3 = ex2f(s[nb * 4 + 3]);
                if (msk) {
                    if (k0     > qrow0) p0 = 0.f;
                    if (k0 + 1 > qrow0) p1 = 0.f;
                    if (k0     > qrow1) p2 = 0.f;
                    if (k0 + 1 > qrow1) p3 = 0.f;
                }
                s[nb * 4 + 0] = p0; s[nb * 4 + 1] = p1;
                s[nb * 4 + 2] = p2; s[nb * 4 + 3] = p3;
                l0 += p0 + p1;
                l1 += p2 + p3;
            }

            uint32_t ph[4];
            ph[0] = pack_h2(s[0], s[1]);
            ph[1] = pack_h2(s[2], s[3]);
            ph[2] = pack_h2(s[4], s[5]);
            ph[3] = pack_h2(s[6], s[7]);
#pragma unroll
            for (int j = 0; j < 4; j++) {
                uint32_t vh[4];
                ldm_x4(vh, vAddr + j * 16 * 144);
                mma16816(&o[(2 * j) * 4],     ph, vh[0], vh[1]);
                mma16816(&o[(2 * j + 1) * 4], ph, vh[2], vh[3]);
            }
        };

        for (int i = 0; i < npair; i++) {
            if (i + 2 < npair) fill_pair(i + 2);
            CP_COMMIT();

            const uint32_t pbase = sb + (i % 3) * PAIRB;
            const int t0 = 2 * i;
            const bool two = (t0 + 1 < nkt);

            if (w & 1) {
                // odd warps: tile b first -> their QK(b) overlaps even warps'
                // exp/PV(a), and vice versa (anti-phase pipes per SMSP)
                if (two) compute_tile(pbase + SLOTB, t0 + 1);
                compute_tile(pbase, t0);
            } else {
                compute_tile(pbase, t0);
                if (two) compute_tile(pbase + SLOTB, t0 + 1);
            }

            CP_WAIT(1);
            __syncthreads();
        }

        // pass epilogue: tree reduction over 4 column groups, normalize, store
        const int rrow = wr * 32 + ln;
        float* rpA = &redA[rrow * RP];
        float* rpB = &redB[rrow * RP];
        if (wc == 3) {
#pragma unroll
            for (int i = 0; i < 32; i++) rpA[i] = o[i];
            rpA[32] = l0; rpA[33] = l1;
        } else if (wc == 1) {
#pragma unroll
            for (int i = 0; i < 32; i++) rpB[i] = o[i];
            rpB[32] = l0; rpB[33] = l1;
        }
        __syncthreads();
        if (wc == 2) {
#pragma unroll
            for (int i = 0; i < 32; i++) rpA[i] += o[i];
            rpA[32] += l0; rpA[33] += l1;
        } else if (wc == 0) {
#pragma unroll
            for (int i = 0; i < 32; i++) o[i] += rpB[i];
            l0 += rpB[32]; l1 += rpB[33];
        }
        __syncthreads();
        if (wc == 0) {
#pragma unroll
            for (int i = 0; i < 32; i++) o[i] += rpA[i];
            l0 += rpA[32]; l1 += rpA[33];
            l0 += __shfl_xor_sync(0xffffffffu, l0, 1);
            l0 += __shfl_xor_sync(0xffffffffu, l0, 2);
            l1 += __shfl_xor_sync(0xffffffffu, l1, 1);
            l1 += __shfl_xor_sync(0xffffffffu, l1, 2);
            const float i0 = 1.f / l0;
            const float i1 = 1.f / l1;
            float* Og = out + ((size_t)b * SEQ + qt * 64 + wr * 16 + g) * HD;
#pragma unroll
            for (int nb = 0; nb < 8; nb++) {
                int hc = nb * 8 + t4 * 2;
                *(float2*)&Og[hc] =
                    make_float2(o[nb * 4 + 0] * i0, o[nb * 4 + 1] * i0);
                *(float2*)&Og[8 * HD + hc] =
                    make_float2(o[nb * 4 + 2] * i1, o[nb * 4 + 3] * i1);
            }
        }
        __syncthreads();
    }
}

// ---------------------------------------------------------------------------
extern "C" void kernel_launch(void* const* d_in, const int* in_sizes, int n_in,
                              void* d_out, int out_size)
{
    const float* x  = (const float*)d_in[0];
    const float* Wq = (const float*)d_in[1];
    const float* bq = (const float*)d_in[2];
    const float* Wk = (const float*)d_in[3];
    const float* bk = (const float*)d_in[4];
    const float* Wv = (const float*)d_in[5];
    const float* bv = (const float*)d_in[6];
    float* out = (float*)d_out;

    wsplit_kernel<<<dim3(3, 16), 256>>>(Wq, Wk, Wv);

    cudaFuncSetAttribute(qkv_mma7,
                         cudaFuncAttributeMaxDynamicSharedMemorySize, QKV_SMEM);
    qkv_mma7<<<dim3(3, ROWS / 128), 256, QKV_SMEM>>>(x, bq, bk, bv);

    cudaFuncSetAttribute(flash_mmaB,
                         cudaFuncAttributeMaxDynamicSharedMemorySize, FLASH_SMEM);
    flash_mmaB<<<dim3(32, BATCH), 512, FLASH_SMEM>>>(out);
}

// round 17
// speedup vs baseline: 1.0172x; 1.0172x over previous
#include <cuda_runtime.h>
#include <cuda_fp16.h>
#include <cstdint>
#include <math.h>

// Problem constants
constexpr int BATCH = 4;
constexpr int SEQ   = 4096;
constexpr int EMB   = 1024;
constexpr int HD    = 64;
constexpr int ROWS  = BATCH * SEQ;

constexpr int P32  = 36;            // u32 pitch for 64-col f16 tile rows
constexpr int PH   = 72;            // same pitch in halves
constexpr int TSZ  = 64 * P32;      // u32 per tile component (2304)
constexpr int TSZB = TSZ * 4;       // bytes (9216)
constexpr int SLOTB = 2 * TSZB;     // K hi + V^T hi per tile slot (18432)

// Pre-split fp16 scratch (device globals; 16B aligned for cp.async)
__device__ __align__(16) uint32_t g_Qhi[ROWS * 32];             // Q*0.125, fp16
__device__ __align__(16) uint32_t g_Ksp[BATCH * 64 * TSZ];      // [tile] K-major hi
__device__ __align__(16) uint32_t g_Vsp[BATCH * 64 * TSZ];      // [tile] V^T hi
__device__ __align__(16) uint32_t g_Wsp[3 * 16 * 2 * TSZ];      // W^T fp16 image per chunk

// ---------------------------------------------------------------------------
// helpers
// ---------------------------------------------------------------------------
__device__ __forceinline__ uint32_t pack_h2(float a, float b) {
    uint32_t h;
    asm("cvt.rn.f16x2.f32 %0, %1, %2;" : "=r"(h) : "f"(b), "f"(a));
    return h;   // low half = a, high half = b
}
__device__ __forceinline__ void split2pack(float a, float b,
                                           uint32_t& hi, uint32_t& lo) {
    hi = pack_h2(a, b);
    __half2 h2 = *(__half2*)&hi;
    lo = pack_h2(a - __low2float(h2), b - __high2float(h2));
}

__device__ __forceinline__ void mma16816(float* d, const uint32_t* a,
                                         uint32_t b0, uint32_t b1) {
    asm volatile(
        "mma.sync.aligned.m16n8k16.row.col.f32.f16.f16.f32 "
        "{%0,%1,%2,%3}, {%4,%5,%6,%7}, {%8,%9}, {%0,%1,%2,%3};"
        : "+f"(d[0]), "+f"(d[1]), "+f"(d[2]), "+f"(d[3])
        : "r"(a[0]), "r"(a[1]), "r"(a[2]), "r"(a[3]), "r"(b0), "r"(b1));
}

__device__ __forceinline__ void ldm_x4(uint32_t* r, uint32_t addr) {
    asm volatile("ldmatrix.sync.aligned.m8n8.x4.shared.b16 {%0,%1,%2,%3}, [%4];"
                 : "=r"(r[0]), "=r"(r[1]), "=r"(r[2]), "=r"(r[3]) : "r"(addr));
}

__device__ __forceinline__ void cpasync16(uint32_t saddr, const void* gptr) {
    asm volatile("cp.async.cg.shared.global [%0], [%1], 16;"
                 :: "r"(saddr), "l"(gptr) : "memory");
}
#define CP_COMMIT() asm volatile("cp.async.commit_group;" ::: "memory")
#define CP_WAIT(n)  asm volatile("cp.async.wait_group %0;" :: "n"(n) : "memory")

// ---------------------------------------------------------------------------
// Kernel 0: pre-split W^T fp16 images, smem-staged so global stores coalesce.
// ---------------------------------------------------------------------------
__global__ __launch_bounds__(256) void wsplit_kernel(
    const float* __restrict__ Wq, const float* __restrict__ Wk,
    const float* __restrict__ Wv)
{
    __shared__ float ws[64 * 65];
    const int m  = blockIdx.x;
    const int kb = blockIdx.y;
    const float* W = (m == 0) ? Wq : (m == 1) ? Wk : Wv;
    const int tid = threadIdx.x;

#pragma unroll
    for (int i = 0; i < 4; i++) {
        int idx = tid + i * 256;
        int r   = idx >> 4;
        int c4  = (idx & 15) * 4;
        float4 v = *(const float4*)&W[(size_t)(kb * 64 + r) * HD + c4];
        float* d = &ws[r * 65 + c4];
        d[0] = v.x; d[1] = v.y; d[2] = v.z; d[3] = v.w;
    }
    __syncthreads();

    uint32_t* hiO = g_Wsp + (size_t)(m * 16 + kb) * 2 * TSZ;
    uint32_t* loO = hiO + TSZ;
#pragma unroll
    for (int i = 0; i < 8; i++) {
        int idx = tid + i * 256;
        int c   = idx >> 5;
        int rp  = idx & 31;
        float a = ws[(rp * 2) * 65 + c];
        float b = ws[(rp * 2 + 1) * 65 + c];
        uint32_t h, l;
        split2pack(a, b, h, l);
        hiO[c * P32 + rp] = h;
        loO[c * P32 + rp] = l;
    }
}

// ---------------------------------------------------------------------------
// Kernel 1: QKV projection, 2-term fp16 split (EXACT R12 structure/numerics).
// grid (3, 128), 3 CTAs/SM.  Q output pre-scaled by 0.125 (exact).
// ---------------------------------------------------------------------------
constexpr int QKV_SMEM = (128 * P32 + 2 * TSZ) * 4;   // 36864 B

__global__ __launch_bounds__(256, 3) void qkv_mma7(
    const float* __restrict__ x,
    const float* __restrict__ bq, const float* __restrict__ bk,
    const float* __restrict__ bv)
{
    extern __shared__ __align__(16) uint32_t qsm[];
    uint32_t* sXhi = qsm;
    const uint32_t sb    = (uint32_t)__cvta_generic_to_shared(qsm);
    const uint32_t sXhiB = sb;
    const uint32_t sWhB  = sb + 128 * P32 * 4;
    const uint32_t sWlB  = sWhB + TSZB;

    const int tid = threadIdx.x;
    const int w   = tid >> 5;
    const int ln  = tid & 31;
    const int g   = ln >> 2;
    const int t4  = ln & 3;
    const int m    = blockIdx.x;
    const int row0 = blockIdx.y * 128;

    const int roA = ((ln >> 3) & 1) * 8 + (ln & 7);
    const int kbA = ((ln >> 4) & 1) * 16;
    const int roB = ((ln >> 4) & 1) * 8 + (ln & 7);
    const int kbB = ((ln >> 3) & 1) * 16;
    const uint32_t aHi = sXhiB + (w * 16 + roA) * 144 + kbA;
    const uint32_t bHi = sWhB + roB * 144 + kbB;
    const uint32_t bLo = sWlB + roB * 144 + kbB;

    float acc[32];
#pragma unroll
    for (int i = 0; i < 32; i++) acc[i] = 0.f;

    for (int kb = 0; kb < 16; kb++) {
        {
            const char* src = (const char*)(g_Wsp + (size_t)(m * 16 + kb) * 2 * TSZ);
            for (int i = tid; i < 1152; i += 256)
                cpasync16(sWhB + i * 16, src + i * 16);
            CP_COMMIT();
        }
        // stage x tile 128x64, hi only
#pragma unroll
        for (int i = 0; i < 8; i++) {
            int idx = tid + i * 256;
            int r   = idx >> 4;
            int c4  = (idx & 15) * 4;
            float4 v = *(const float4*)&x[(size_t)(row0 + r) * EMB + kb * 64 + c4];
            int o = r * P32 + (c4 >> 1);
            sXhi[o]     = pack_h2(v.x, v.y);
            sXhi[o + 1] = pack_h2(v.z, v.w);
        }
        CP_WAIT(0);
        __syncthreads();

#pragma unroll
        for (int kk = 0; kk < 4; kk++) {
            uint32_t ah[4];
            ldm_x4(ah, aHi + kk * 32);
#pragma unroll
            for (int j = 0; j < 4; j++) {
                uint32_t bh[4], bl[4];
                ldm_x4(bh, bHi + j * 16 * 144 + kk * 32);
                ldm_x4(bl, bLo + j * 16 * 144 + kk * 32);
                float* d0 = &acc[(2 * j) * 4];
                float* d1 = &acc[(2 * j + 1) * 4];
                mma16816(d0, ah, bh[0], bh[1]);
                mma16816(d0, ah, bl[0], bl[1]);
                mma16816(d1, ah, bh[2], bh[3]);
                mma16816(d1, ah, bl[2], bl[3]);
            }
        }
        __syncthreads();
    }

    // epilogue: bias (+0.125 scale for Q) + fp16 round + store images
    const int r0  = row0 + w * 16 + g;
    const int ktf = r0 >> 6;
    const int rr  = r0 & 63;

    if (m == 0) {
#pragma unroll
        for (int nb = 0; nb < 8; nb++) {
            int hc = nb * 8 + t4 * 2;
            float2 bb = *(const float2*)&bq[hc];
            g_Qhi[(size_t)r0 * 32 + (hc >> 1)] =
                pack_h2((acc[nb * 4 + 0] + bb.x) * 0.125f,
                        (acc[nb * 4 + 1] + bb.y) * 0.125f);
            g_Qhi[(size_t)(r0 + 8) * 32 + (hc >> 1)] =
                pack_h2((acc[nb * 4 + 2] + bb.x) * 0.125f,
                        (acc[nb * 4 + 3] + bb.y) * 0.125f);
        }
    } else if (m == 1) {
        uint32_t* kHI = g_Ksp + (size_t)ktf * TSZ;
#pragma unroll
        for (int nb = 0; nb < 8; nb++) {
            int hc = nb * 8 + t4 * 2;
            float2 bb = *(const float2*)&bk[hc];
            kHI[rr * P32 + (hc >> 1)] =
                pack_h2(acc[nb * 4 + 0] + bb.x, acc[nb * 4 + 1] + bb.y);
            kHI[(rr + 8) * P32 + (hc >> 1)] =
                pack_h2(acc[nb * 4 + 2] + bb.x, acc[nb * 4 + 3] + bb.y);
        }
    } else {
        unsigned short* vHI = (unsigned short*)(g_Vsp + (size_t)ktf * TSZ);
#pragma unroll
        for (int nb = 0; nb < 8; nb++) {
            int hc = nb * 8 + t4 * 2;
            float2 bb = *(const float2*)&bv[hc];
            uint32_t h = pack_h2(acc[nb * 4 + 0] + bb.x, acc[nb * 4 + 1] + bb.y);
            vHI[hc * PH + rr]       = (unsigned short)(h & 0xffff);
            vHI[(hc + 1) * PH + rr] = (unsigned short)(h >> 16);
            h = pack_h2(acc[nb * 4 + 2] + bb.x, acc[nb * 4 + 3] + bb.y);
            vHI[hc * PH + rr + 8]       = (unsigned short)(h & 0xffff);
            vHI[(hc + 1) * PH + rr + 8] = (unsigned short)(h >> 16);
        }
    }
}

// ---------------------------------------------------------------------------
// Kernel 2: balanced causal flash attention, QUAD-tile iterations.
// Four 64-key tiles per loop body; 3-quad cp.async ring; ONE sync per quad
// (17 syncs/CTA vs 33 with pairs).  Epilogue reduction buffers OVERLAY quad
// slot 0 (dead by then; guarded by CP_WAIT(0)+sync).
// Numerics identical to R12 (expf, Q pre-scaled 0.125).
// 512 thr, grid (32, BATCH).
// ---------------------------------------------------------------------------
constexpr int RP = 37;
constexpr int QUADB = 4 * SLOTB;                    // 73728 B
constexpr int FLASH_SMEM = 3 * QUADB;               // 221184 B (red overlays slot0)

__global__ __launch_bounds__(512) void flash_mmaC(float* __restrict__ out)
{
    extern __shared__ __align__(16) uint32_t fsm[];
    float* redA = (float*)fsm;                       // overlays quad slot 0
    float* redB = redA + 128 * RP;

    const uint32_t sb = (uint32_t)__cvta_generic_to_shared(fsm);
    const int tid = threadIdx.x;
    const int w   = tid >> 5;
    const int ln  = tid & 31;
    const int g   = ln >> 2;
    const int t4  = ln & 3;
    const int wr  = w & 3;
    const int wc  = w >> 2;
    const int c   = blockIdx.x;
    const int b   = blockIdx.y;

    const int roB = ((ln >> 4) & 1) * 8 + (ln & 7);
    const int kbB = ((ln >> 3) & 1) * 16;

    const int qts[2] = {c, 63 - c};

    for (int p = 0; p < 2; p++) {
        const int qt    = qts[p];
        const int nkt   = qt + 1;
        const int nquad = (nkt + 3) >> 2;

        const size_t rowg = (size_t)b * SEQ + qt * 64 + wr * 16 + g;
        uint32_t qfh[16];
#pragma unroll
        for (int kk = 0; kk < 4; kk++) {
            qfh[kk * 4 + 0] = g_Qhi[rowg * 32 + kk * 8 + t4];
            qfh[kk * 4 + 1] = g_Qhi[(rowg + 8) * 32 + kk * 8 + t4];
            qfh[kk * 4 + 2] = g_Qhi[rowg * 32 + kk * 8 + t4 + 4];
            qfh[kk * 4 + 3] = g_Qhi[(rowg + 8) * 32 + kk * 8 + t4 + 4];
        }

        float o[32];
#pragma unroll
        for (int i = 0; i < 32; i++) o[i] = 0.f;
        float l0 = 0.f, l1 = 0.f;
        const int qrow0 = qt * 64 + wr * 16 + g;
        const int qrow1 = qrow0 + 8;

        auto fill_tile = [&](uint32_t d, int t) {
            const char* sK = (const char*)(g_Ksp + (size_t)(b * 64 + t) * TSZ);
            const char* sV = (const char*)(g_Vsp + (size_t)(b * 64 + t) * TSZ);
            for (int i = tid; i < 576; i += 512)
                cpasync16(d + i * 16, sK + i * 16);
            for (int i = tid; i < 576; i += 512)
                cpasync16(d + TSZB + i * 16, sV + i * 16);
        };
        // fill quad qd (tiles 4qd..4qd+3, clamped to valid memory t<64)
        auto fill_quad = [&](int qd) {
            uint32_t d = sb + (qd % 3) * QUADB;
            int t0 = 4 * qd;
#pragma unroll
            for (int j = 0; j < 4; j++)
                if (t0 + j < 64) fill_tile(d + j * SLOTB, t0 + j);
        };

        fill_quad(0);
        CP_COMMIT();
        if (nquad > 1) fill_quad(1);
        CP_COMMIT();
        CP_WAIT(1);
        __syncthreads();

        auto compute_tile = [&](uint32_t base, int kt) {
            const uint32_t kAddr = base + (wc * 16 + roB) * 144 + kbB;
            const uint32_t vAddr = base + TSZB + roB * 144 + wc * 32 + kbB;

            float s[8];
#pragma unroll
            for (int i = 0; i < 8; i++) s[i] = 0.f;
#pragma unroll
            for (int kk = 0; kk < 4; kk++) {
                uint32_t bh[4];
                ldm_x4(bh, kAddr + kk * 32);
                const uint32_t* ah = &qfh[kk * 4];
                mma16816(&s[0], ah, bh[0], bh[1]);
                mma16816(&s[4], ah, bh[2], bh[3]);
            }

            const bool msk = (kt == qt);
#pragma unroll
            for (int nb = 0; nb < 2; nb++) {
                int k0 = kt * 64 + wc * 16 + nb * 8 + t4 * 2;
                float p0 = __expf(s[nb * 4 + 0]);
                float p1 = __expf(s[nb * 4 + 1]);
                float p2 = __expf(s[nb * 4 + 2]);
                float p3 = __expf(s[nb * 4 + 3]);
                if (msk) {
                    if (k0     > qrow0) p0 = 0.f;
                    if (k0 + 1 > qrow0) p1 = 0.f;
                    if (k0     > qrow1) p2 = 0.f;
                    if (k0 + 1 > qrow1) p3 = 0.f;
                }
                s[nb * 4 + 0] = p0; s[nb * 4 + 1] = p1;
                s[nb * 4 + 2] = p2; s[nb * 4 + 3] = p3;
                l0 += p0 + p1;
                l1 += p2 + p3;
            }

            uint32_t ph[4];
            ph[0] = pack_h2(s[0], s[1]);
            ph[1] = pack_h2(s[2], s[3]);
            ph[2] = pack_h2(s[4], s[5]);
            ph[3] = pack_h2(s[6], s[7]);
#pragma unroll
            for (int j = 0; j < 4; j++) {
                uint32_t vh[4];
                ldm_x4(vh, vAddr + j * 16 * 144);
                mma16816(&o[(2 * j) * 4],     ph, vh[0], vh[1]);
                mma16816(&o[(2 * j + 1) * 4], ph, vh[2], vh[3]);
            }
        };

        for (int i = 0; i < nquad; i++) {
            if (i + 2 < nquad) fill_quad(i + 2);
            CP_COMMIT();

            const uint32_t qbase = sb + (i % 3) * QUADB;
            const int t0 = 4 * i;
            compute_tile(qbase, t0);
            if (t0 + 1 < nkt) compute_tile(qbase + SLOTB, t0 + 1);
            if (t0 + 2 < nkt) compute_tile(qbase + 2 * SLOTB, t0 + 2);
            if (t0 + 3 < nkt) compute_tile(qbase + 3 * SLOTB, t0 + 3);

            CP_WAIT(1);
            __syncthreads();
        }

        // drain all pending fills before reusing slot 0 memory for reduction
        CP_WAIT(0);
        __syncthreads();

        // pass epilogue: tree reduction over 4 column groups, normalize, store
        const int rrow = wr * 32 + ln;
        float* rpA = &redA[rrow * RP];
        float* rpB = &redB[rrow * RP];
        if (wc == 3) {
#pragma unroll
            for (int i = 0; i < 32; i++) rpA[i] = o[i];
            rpA[32] = l0; rpA[33] = l1;
        } else if (wc == 1) {
#pragma unroll
            for (int i = 0; i < 32; i++) rpB[i] = o[i];
            rpB[32] = l0; rpB[33] = l1;
        }
        __syncthreads();
        if (wc == 2) {
#pragma unroll
            for (int i = 0; i < 32; i++) rpA[i] += o[i];
            rpA[32] += l0; rpA[33] += l1;
        } else if (wc == 0) {
#pragma unroll
            for (int i = 0; i < 32; i++) o[i] += rpB[i];
            l0 += rpB[32]; l1 += rpB[33];
        }
        __syncthreads();
        if (wc == 0) {
#pragma unroll
            for (int i = 0; i < 32; i++) o[i] += rpA[i];
            l0 += rpA[32]; l1 += rpA[33];
            l0 += __shfl_xor_sync(0xffffffffu, l0, 1);
            l0 += __shfl_xor_sync(0xffffffffu, l0, 2);
            l1 += __shfl_xor_sync(0xffffffffu, l1, 1);
            l1 += __shfl_xor_sync(0xffffffffu, l1, 2);
            const float i0 = 1.f / l0;
            const float i1 = 1.f / l1;
            float* Og = out + ((size_t)b * SEQ + qt * 64 + wr * 16 + g) * HD;
#pragma unroll
            for (int nb = 0; nb < 8; nb++) {
                int hc = nb * 8 + t4 * 2;
                *(float2*)&Og[hc] =
                    make_float2(o[nb * 4 + 0] * i0, o[nb * 4 + 1] * i0);
                *(float2*)&Og[8 * HD + hc] =
                    make_float2(o[nb * 4 + 2] * i1, o[nb * 4 + 3] * i1);
            }
        }
        __syncthreads();   // red overlay free before next pass refills slot 0
    }
}

// ---------------------------------------------------------------------------
extern "C" void kernel_launch(void* const* d_in, const int* in_sizes, int n_in,
                              void* d_out, int out_size)
{
    const float* x  = (const float*)d_in[0];
    const float* Wq = (const float*)d_in[1];
    const float* bq = (const float*)d_in[2];
    const float* Wk = (const float*)d_in[3];
    const float* bk = (const float*)d_in[4];
    const float* Wv = (const float*)d_in[5];
    const float* bv = (const float*)d_in[6];
    float* out = (float*)d_out;

    wsplit_kernel<<<dim3(3, 16), 256>>>(Wq, Wk, Wv);

    cudaFuncSetAttribute(qkv_mma7,
                         cudaFuncAttributeMaxDynamicSharedMemorySize, QKV_SMEM);
    qkv_mma7<<<dim3(3, ROWS / 128), 256, QKV_SMEM>>>(x, bq, bk, bv);

    cudaFuncSetAttribute(flash_mmaC,
                         cudaFuncAttributeMaxDynamicSharedMemorySize, FLASH_SMEM);
    flash_mmaC<<<dim3(32, BATCH), 512, FLASH_SMEM>>>(out);
}